// round 6
// baseline (speedup 1.0000x reference)
#include <cuda_runtime.h>
#include <cstdint>
#include <math.h>

#define BATCH 8
#define NPTS  4096
#define M1    2048
#define M2    512
#define KNB   64

// ----------------------------------------------------------------------------
// Scratch (device globals; no allocations allowed)
// ----------------------------------------------------------------------------
static __device__ float    g_cent1[BATCH * M1 * 3];
static __device__ int      g_nbr1 [BATCH * M1 * KNB];
static __device__ int      g_cnt1 [BATCH * M1];
static __device__ float    g_x1   [BATCH * M1 * 64];
static __device__ float    g_cent2[BATCH * M2 * 3];
static __device__ int      g_nbr2 [BATCH * M2 * KNB];
static __device__ int      g_cnt2 [BATCH * M2];
static __device__ float    g_x2   [BATCH * M2 * 128];
static __device__ unsigned g_featEnc[BATCH * 512];

// ----------------------------------------------------------------------------
// Helpers
// ----------------------------------------------------------------------------
__device__ __forceinline__ float d2_ref(float dx, float dy, float dz) {
    // XLA-style fused emission of sum((p-c)**2) over size-3 axis
    return __fmaf_rn(dz, dz, __fmaf_rn(dy, dy, __fmul_rn(dx, dx)));
}

__device__ __forceinline__ unsigned encf(float f) {
    unsigned u = __float_as_uint(f);
    return (u & 0x80000000u) ? ~u : (u | 0x80000000u);
}
__device__ __forceinline__ float decf(unsigned u) {
    return (u & 0x80000000u) ? __uint_as_float(u & 0x7FFFFFFFu) : __uint_as_float(~u);
}

// ----------------------------------------------------------------------------
// FPS: one block per batch, sequential farthest point sampling.
// ----------------------------------------------------------------------------
__global__ void fps_kernel(const float* __restrict__ pos_ext, int level, int N, int M)
{
    extern __shared__ float spos[];  // N*3 floats
    __shared__ unsigned long long wred[16];
    __shared__ float fpos[3];

    const float* srcbase = (level == 0) ? pos_ext : g_cent1;
    float* cent_out      = (level == 0) ? g_cent1 : g_cent2;

    const int b = blockIdx.x, tid = threadIdx.x, nt = blockDim.x;
    const float* P = srcbase + (size_t)b * N * 3;
    for (int i = tid; i < N * 3; i += nt) spos[i] = P[i];
    __syncthreads();

    float lx[8], ly[8], lz[8], ld[8];
    const int KP = (N + nt - 1) / nt;
    for (int k = 0; k < KP; ++k) {
        int p = tid + k * nt;
        if (p < N) { lx[k] = spos[p*3]; ly[k] = spos[p*3+1]; lz[k] = spos[p*3+2]; }
        ld[k] = __int_as_float(0x7f800000);  // +inf
    }
    if (tid == 0) { fpos[0] = spos[0]; fpos[1] = spos[1]; fpos[2] = spos[2]; }
    __syncthreads();

    const int lane = tid & 31, warp = tid >> 5, nw = nt >> 5;

    for (int t = 0; t < M; ++t) {
        float cx = fpos[0], cy = fpos[1], cz = fpos[2];
        if (tid == 0) {
            int o = b * M + t;
            cent_out[o*3] = cx; cent_out[o*3+1] = cy; cent_out[o*3+2] = cz;
        }
        unsigned long long best = 0ULL;
        for (int k = 0; k < KP; ++k) {
            int p = tid + k * nt;
            if (p < N) {
                float d = d2_ref(lx[k]-cx, ly[k]-cy, lz[k]-cz);
                float nd = fminf(ld[k], d);
                ld[k] = nd;
                unsigned long long key =
                    (((unsigned long long)__float_as_uint(nd)) << 32) |
                    (unsigned)(0xFFFFFFFFu - (unsigned)p);   // tie -> lowest index wins max
                best = (key > best) ? key : best;
            }
        }
        #pragma unroll
        for (int o = 16; o > 0; o >>= 1) {
            unsigned long long v = __shfl_down_sync(0xFFFFFFFFu, best, o);
            best = (v > best) ? v : best;
        }
        if (lane == 0) wred[warp] = best;
        __syncthreads();
        if (tid == 0) {
            unsigned long long m = wred[0];
            for (int w = 1; w < nw; ++w) m = (wred[w] > m) ? wred[w] : m;
            int far = (int)(0xFFFFFFFFu - (unsigned)(m & 0xFFFFFFFFu));
            fpos[0] = spos[far*3]; fpos[1] = spos[far*3+1]; fpos[2] = spos[far*3+2];
        }
        __syncthreads();
    }
}

// ----------------------------------------------------------------------------
// Radius-limited K smallest neighbors. One block per center.
// ----------------------------------------------------------------------------
__global__ void knn_kernel(const float* __restrict__ pos_ext, int level, int N, int M, float R2)
{
    extern __shared__ unsigned long long keys[];  // N entries
    __shared__ int scnt;

    const float* pts     = (level == 0) ? pos_ext : g_cent1;
    const float* centers = (level == 0) ? g_cent1 : g_cent2;
    int* nbr             = (level == 0) ? g_nbr1  : g_nbr2;
    int* cnt             = (level == 0) ? g_cnt1  : g_cnt2;

    const int bm = blockIdx.x;      // b*M + m
    const int b  = bm / M;
    const int tid = threadIdx.x, nt = blockDim.x;
    const float* P = pts + (size_t)b * N * 3;
    const float cx = centers[bm*3], cy = centers[bm*3+1], cz = centers[bm*3+2];

    if (tid == 0) scnt = 0;
    __syncthreads();

    for (int p = tid; p < N; p += nt) {
        float d2 = d2_ref(P[p*3]-cx, P[p*3+1]-cy, P[p*3+2]-cz);
        if (d2 <= R2) {
            int q = atomicAdd(&scnt, 1);
            keys[q] = (((unsigned long long)__float_as_uint(d2)) << 32) | (unsigned)p;
        }
    }
    __syncthreads();
    const int C  = scnt;
    const int KO = (C < KNB) ? C : KNB;

    if (C > KNB) {
        int Pow = 1; while (Pow < C) Pow <<= 1;
        for (int i = C + tid; i < Pow; i += nt) keys[i] = ~0ULL;
        __syncthreads();
        for (int size = 2; size <= Pow; size <<= 1) {
            for (int stride = size >> 1; stride > 0; stride >>= 1) {
                for (int t2 = tid; t2 < (Pow >> 1); t2 += nt) {
                    int lo = (t2 << 1) - (t2 & (stride - 1));
                    int hi = lo + stride;
                    unsigned long long a = keys[lo], c2 = keys[hi];
                    bool asc = ((lo & size) == 0);
                    if ((a > c2) == asc) { keys[lo] = c2; keys[hi] = a; }
                }
                __syncthreads();
            }
        }
    }

    for (int k = tid; k < KNB; k += nt)
        nbr[(size_t)bm * KNB + k] = (k < KO) ? (int)(unsigned)(keys[k] & 0xFFFFFFFFu) : 0;
    if (tid == 0) cnt[bm] = KO;
}

// ----------------------------------------------------------------------------
// Generic shared->shared MLP layer. Weights from global (L1-resident, float4).
// ----------------------------------------------------------------------------
__device__ __forceinline__ void mlp_layer(
    const float* __restrict__ Fin, float* __restrict__ Fout,
    const float* __restrict__ w, const float* __restrict__ bias,
    int rows, int din, int dout, bool do_relu)
{
    const int tid = threadIdx.x, nt = blockDim.x;
    const int jb = dout >> 2;
    const int total = rows * jb;
    for (int it = tid; it < total; it += nt) {
        int n = it / jb;
        int j = (it - n * jb) << 2;
        const float* fr = Fin + n * din;
        float4 acc;
        acc.x = __ldg(bias + j);     acc.y = __ldg(bias + j + 1);
        acc.z = __ldg(bias + j + 2); acc.w = __ldg(bias + j + 3);
        #pragma unroll 4
        for (int i = 0; i < din; ++i) {
            float f = fr[i];
            float4 wv = __ldg(reinterpret_cast<const float4*>(w + (size_t)i * dout + j));
            acc.x = fmaf(f, wv.x, acc.x);
            acc.y = fmaf(f, wv.y, acc.y);
            acc.z = fmaf(f, wv.z, acc.z);
            acc.w = fmaf(f, wv.w, acc.w);
        }
        if (do_relu) {
            acc.x = fmaxf(acc.x, 0.f); acc.y = fmaxf(acc.y, 0.f);
            acc.z = fmaxf(acc.z, 0.f); acc.w = fmaxf(acc.w, 0.f);
        }
        float* o = Fout + n * dout + j;
        o[0] = acc.x; o[1] = acc.y; o[2] = acc.z; o[3] = acc.w;
    }
}

// ----------------------------------------------------------------------------
// SA1: per-center MLP(3->32->32->64) over 64 neighbors + masked max.
// ----------------------------------------------------------------------------
__global__ void sa1_kernel(const float* __restrict__ pos,
                           const float* __restrict__ w0, const float* __restrict__ b0,
                           const float* __restrict__ w1, const float* __restrict__ b1,
                           const float* __restrict__ w2, const float* __restrict__ b2)
{
    __shared__ float F0[64 * 3];
    __shared__ float FA[64 * 32];
    __shared__ float FB[64 * 32];
    __shared__ float FC[64 * 64];
    const int bm = blockIdx.x;      // b*M1 + m
    const int b  = bm / M1;
    const int tid = threadIdx.x;
    const int C = g_cnt1[bm];

    if (tid < 64) {
        int n = tid;
        float rx = 0.f, ry = 0.f, rz = 0.f;
        if (n < C) {
            int q = g_nbr1[(size_t)bm * KNB + n];
            const float* pp = pos + ((size_t)b * NPTS + q) * 3;
            rx = pp[0] - g_cent1[bm*3];
            ry = pp[1] - g_cent1[bm*3+1];
            rz = pp[2] - g_cent1[bm*3+2];
        }
        F0[n*3] = rx; F0[n*3+1] = ry; F0[n*3+2] = rz;
    }
    __syncthreads();
    mlp_layer(F0, FA, w0, b0, 64, 3, 32, true);   __syncthreads();
    mlp_layer(FA, FB, w1, b1, 64, 32, 32, true);  __syncthreads();
    mlp_layer(FB, FC, w2, b2, 64, 32, 64, false); __syncthreads();
    for (int j = tid; j < 64; j += blockDim.x) {
        float m = FC[j];
        for (int n = 1; n < C; ++n) m = fmaxf(m, FC[n*64 + j]);
        g_x1[(size_t)bm * 64 + j] = m;
    }
}

// ----------------------------------------------------------------------------
// SA2: per-center MLP(67->64->64->128) over 64 neighbors + masked max.
// ----------------------------------------------------------------------------
__global__ void sa2_kernel(const float* __restrict__ w0, const float* __restrict__ b0,
                           const float* __restrict__ w1, const float* __restrict__ b1,
                           const float* __restrict__ w2, const float* __restrict__ b2)
{
    extern __shared__ float sm2[];
    float* bufA = sm2;              // 64*128
    float* bufB = sm2 + 64 * 128;   // 64*128
    __shared__ float srel[64 * 3];
    __shared__ int   sq[64];
    const int bm = blockIdx.x;      // b*M2 + m
    const int b  = bm / M2;
    const int tid = threadIdx.x;
    const int C = g_cnt2[bm];

    if (tid < 64) {
        int n = tid;
        int q = 0; float rx = 0.f, ry = 0.f, rz = 0.f;
        if (n < C) {
            q = g_nbr2[(size_t)bm * KNB + n];
            const float* pp = g_cent1 + ((size_t)b * M1 + q) * 3;
            rx = pp[0] - g_cent2[bm*3];
            ry = pp[1] - g_cent2[bm*3+1];
            rz = pp[2] - g_cent2[bm*3+2];
        }
        sq[n] = q; srel[n*3] = rx; srel[n*3+1] = ry; srel[n*3+2] = rz;
    }
    __syncthreads();
    // F0 = [x_j(64), rel(3)]  width 67
    for (int e = tid; e < 64 * 67; e += blockDim.x) {
        int n = e / 67, i = e - n * 67;
        float v = 0.f;
        if (n < C) v = (i < 64) ? g_x1[((size_t)b * M1 + sq[n]) * 64 + i] : srel[n*3 + (i - 64)];
        bufA[n*67 + i] = v;
    }
    __syncthreads();
    mlp_layer(bufA, bufB, w0, b0, 64, 67, 64, true);   __syncthreads();
    mlp_layer(bufB, bufA, w1, b1, 64, 64, 64, true);   __syncthreads();
    mlp_layer(bufA, bufB, w2, b2, 64, 64, 128, false); __syncthreads();
    for (int j = tid; j < 128; j += blockDim.x) {
        float m = bufB[j];
        for (int n = 1; n < C; ++n) m = fmaxf(m, bufB[n*128 + j]);
        g_x2[(size_t)bm * 128 + j] = m;
    }
}

// ----------------------------------------------------------------------------
// SA3 + global max pool: MLP(131->128->256->512) per point, atomic-max pool.
// ----------------------------------------------------------------------------
__global__ void zero_feat_kernel()
{
    int i = blockIdx.x * blockDim.x + threadIdx.x;
    if (i < BATCH * 512) g_featEnc[i] = 0u;
}

__global__ void sa3_kernel(const float* __restrict__ w0, const float* __restrict__ b0,
                           const float* __restrict__ w1, const float* __restrict__ b1,
                           const float* __restrict__ w2, const float* __restrict__ b2)
{
    extern __shared__ float sm3[];
    float* bufA = sm3;              // 16*512
    float* bufB = sm3 + 16 * 512;   // 16*512
    const int b  = blockIdx.x >> 5;             // 32 blocks per batch
    const int m0 = (blockIdx.x & 31) * 16;
    const int tid = threadIdx.x;

    for (int e = tid; e < 16 * 131; e += blockDim.x) {
        int n = e / 131, i = e - n * 131;
        int m = m0 + n;
        float v = (i < 128) ? g_x2[((size_t)b * M2 + m) * 128 + i]
                            : g_cent2[((size_t)b * M2 + m) * 3 + (i - 128)];
        bufA[n*131 + i] = v;
    }
    __syncthreads();
    mlp_layer(bufA, bufB, w0, b0, 16, 131, 128, true);  __syncthreads();
    mlp_layer(bufB, bufA, w1, b1, 16, 128, 256, true);  __syncthreads();
    mlp_layer(bufA, bufB, w2, b2, 16, 256, 512, false); __syncthreads();
    for (int j = tid; j < 512; j += blockDim.x) {
        float m = bufB[j];
        #pragma unroll
        for (int n = 1; n < 16; ++n) m = fmaxf(m, bufB[n*512 + j]);
        atomicMax(&g_featEnc[b * 512 + j], encf(m));
    }
}

// ----------------------------------------------------------------------------
// Head: mu/logvar linear + reparameterization.
// eps reproduces jax.random.normal(key(42), (8,32)) under the
// threefry_partitionable scheme (JAX >= 0.4.36 default):
//   per element e: (b1,b2) = threefry2x32(key=(0,42), counter=(hi32(e)=0, e))
//   bits[e] = b1 ^ b2   (32-bit fold of the two output words)
// ----------------------------------------------------------------------------
__device__ __forceinline__ uint32_t rotl32(uint32_t x, int r) { return (x << r) | (x >> (32 - r)); }

__device__ __forceinline__ void threefry2x32(uint32_t k0, uint32_t k1, uint32_t& x0, uint32_t& x1)
{
    uint32_t ks0 = k0, ks1 = k1, ks2 = k0 ^ k1 ^ 0x1BD11BDAu;
    const int R0[4] = {13, 15, 26, 6};
    const int R1[4] = {17, 29, 16, 24};
    x0 += ks0; x1 += ks1;
    #pragma unroll
    for (int i = 0; i < 5; ++i) {
        #pragma unroll
        for (int rr = 0; rr < 4; ++rr) {
            int r = (i & 1) ? R1[rr] : R0[rr];
            x0 += x1; x1 = rotl32(x1, r); x1 ^= x0;
        }
        uint32_t a = (i % 3 == 0) ? ks1 : ((i % 3 == 1) ? ks2 : ks0);   // ks[(i+1)%3]
        uint32_t c = (i % 3 == 0) ? ks2 : ((i % 3 == 1) ? ks0 : ks1);   // ks[(i+2)%3]
        x0 += a; x1 += c + (uint32_t)(i + 1);
    }
}

__global__ void head_kernel(const float* __restrict__ w_mu, const float* __restrict__ b_mu,
                            const float* __restrict__ w_lv, const float* __restrict__ b_lv,
                            float* __restrict__ out)
{
    __shared__ float feat[512];
    const int b = blockIdx.x, tid = threadIdx.x;  // 32 threads
    for (int i = tid; i < 512; i += 32) feat[i] = decf(g_featEnc[b * 512 + i]);
    __syncthreads();

    const int j = tid;
    float mu = __ldg(b_mu + j), lv = __ldg(b_lv + j);
    #pragma unroll 4
    for (int i = 0; i < 512; ++i) {
        float f = feat[i];
        mu = fmaf(f, __ldg(w_mu + i * 32 + j), mu);
        lv = fmaf(f, __ldg(w_lv + i * 32 + j), lv);
    }

    // partitionable threefry random bits for element e of shape (8,32)
    int e = b * 32 + j;
    uint32_t x0 = 0u;                 // hi32 of 64-bit counter (size 256 -> 0)
    uint32_t x1 = (uint32_t)e;        // lo32 of 64-bit counter
    threefry2x32(0u, 42u, x0, x1);
    uint32_t y = x0 ^ x1;             // 32-bit output fold

    float u01 = __uint_as_float((y >> 9) | 0x3F800000u) - 1.0f;
    const float lo = -0.99999994f;    // nextafter(-1, 0) in f32
    float u = fmaxf(lo, __fmaf_rn(u01, 2.0f, lo));
    float eps = 1.41421356f * erfinvf(u);

    float z = mu + eps * expf(0.5f * lv);
    out[b * 32 + j]        = z;
    out[256 + b * 32 + j]  = mu;
    out[512 + b * 32 + j]  = lv;
}

// ----------------------------------------------------------------------------
// Launch
// ----------------------------------------------------------------------------
extern "C" void kernel_launch(void* const* d_in, const int* in_sizes, int n_in,
                              void* d_out, int out_size)
{
    (void)in_sizes; (void)n_in; (void)out_size;
    const float* pos  = (const float*)d_in[0];
    const float* s1w0 = (const float*)d_in[1];  const float* s1b0 = (const float*)d_in[2];
    const float* s1w1 = (const float*)d_in[3];  const float* s1b1 = (const float*)d_in[4];
    const float* s1w2 = (const float*)d_in[5];  const float* s1b2 = (const float*)d_in[6];
    const float* s2w0 = (const float*)d_in[7];  const float* s2b0 = (const float*)d_in[8];
    const float* s2w1 = (const float*)d_in[9];  const float* s2b1 = (const float*)d_in[10];
    const float* s2w2 = (const float*)d_in[11]; const float* s2b2 = (const float*)d_in[12];
    const float* s3w0 = (const float*)d_in[13]; const float* s3b0 = (const float*)d_in[14];
    const float* s3w1 = (const float*)d_in[15]; const float* s3b1 = (const float*)d_in[16];
    const float* s3w2 = (const float*)d_in[17]; const float* s3b2 = (const float*)d_in[18];
    const float* w_mu = (const float*)d_in[19]; const float* b_mu = (const float*)d_in[20];
    const float* w_lv = (const float*)d_in[21]; const float* b_lv = (const float*)d_in[22];
    float* out = (float*)d_out;

    cudaFuncSetAttribute(fps_kernel, cudaFuncAttributeMaxDynamicSharedMemorySize, 50 * 1024);
    cudaFuncSetAttribute(sa2_kernel, cudaFuncAttributeMaxDynamicSharedMemorySize, 66 * 1024);
    cudaFuncSetAttribute(sa3_kernel, cudaFuncAttributeMaxDynamicSharedMemorySize, 66 * 1024);

    // ---- SA module 1: FPS(4096->2048, r=0.2) ----
    fps_kernel<<<BATCH, 512, NPTS * 3 * sizeof(float)>>>(pos, 0, NPTS, M1);
    knn_kernel<<<BATCH * M1, 128, NPTS * sizeof(unsigned long long)>>>(pos, 0, NPTS, M1, 0.04f);
    sa1_kernel<<<BATCH * M1, 128>>>(pos, s1w0, s1b0, s1w1, s1b1, s1w2, s1b2);

    // ---- SA module 2: FPS(2048->512, r=0.4) ----
    fps_kernel<<<BATCH, 512, M1 * 3 * sizeof(float)>>>(pos, 1, M1, M2);
    knn_kernel<<<BATCH * M2, 128, M1 * sizeof(unsigned long long)>>>(pos, 1, M1, M2, 0.16f);
    sa2_kernel<<<BATCH * M2, 128, 2 * 64 * 128 * sizeof(float)>>>(s2w0, s2b0, s2w1, s2b1, s2w2, s2b2);

    // ---- SA3 MLP + global max pool ----
    zero_feat_kernel<<<(BATCH * 512 + 255) / 256, 256>>>();
    sa3_kernel<<<BATCH * 32, 128, 2 * 16 * 512 * sizeof(float)>>>(s3w0, s3b0, s3w1, s3b1, s3w2, s3b2);

    // ---- head: mu / logvar / reparameterized z ----
    head_kernel<<<BATCH, 32>>>(w_mu, b_mu, w_lv, b_lv, out);
}

// round 7
// speedup vs baseline: 2.9454x; 2.9454x over previous
#include <cuda_runtime.h>
#include <cstdint>
#include <math.h>

#define BATCH 8
#define NPTS  4096
#define M1    2048
#define M2    512
#define KNB   64

// ----------------------------------------------------------------------------
// Scratch (device globals; no allocations allowed)
// ----------------------------------------------------------------------------
static __device__ float    g_cent1[BATCH * M1 * 3];
static __device__ int      g_nbr1 [BATCH * M1 * KNB];
static __device__ int      g_cnt1 [BATCH * M1];
static __device__ float    g_x1   [BATCH * M1 * 64];
static __device__ float    g_cent2[BATCH * M2 * 3];
static __device__ int      g_nbr2 [BATCH * M2 * KNB];
static __device__ int      g_cnt2 [BATCH * M2];
static __device__ float    g_x2   [BATCH * M2 * 128];
static __device__ unsigned g_featEnc[BATCH * 512];

// ----------------------------------------------------------------------------
// Helpers
// ----------------------------------------------------------------------------
__device__ __forceinline__ float d2_ref(float dx, float dy, float dz) {
    // XLA-style fused emission of sum((p-c)**2) over size-3 axis
    return __fmaf_rn(dz, dz, __fmaf_rn(dy, dy, __fmul_rn(dx, dx)));
}

__device__ __forceinline__ unsigned encf(float f) {
    unsigned u = __float_as_uint(f);
    return (u & 0x80000000u) ? ~u : (u | 0x80000000u);
}
__device__ __forceinline__ float decf(unsigned u) {
    return (u & 0x80000000u) ? __uint_as_float(u & 0x7FFFFFFFu) : __uint_as_float(~u);
}

// ----------------------------------------------------------------------------
// FPS: one block (512 thr) per batch. REDUX-based argmax with exact
// max-dist / tie->min-index semantics; one barrier per iteration via
// double-buffered per-warp slots.
// ----------------------------------------------------------------------------
__global__ void fps_kernel(const float* __restrict__ pos_ext, int level, int N, int M)
{
    extern __shared__ float spos[];  // N*3 floats
    __shared__ unsigned long long wred[2][16];

    const float* srcbase = (level == 0) ? pos_ext : g_cent1;
    float* cent_out      = (level == 0) ? g_cent1 : g_cent2;

    const int b = blockIdx.x, tid = threadIdx.x;
    const int nt = 512;
    const float* P = srcbase + (size_t)b * N * 3;
    for (int i = tid; i < N * 3; i += nt) spos[i] = P[i];
    __syncthreads();

    float lx[8], ly[8], lz[8], ld[8];
    const int KP = N / nt;              // 8 (level0) or 4 (level1); exact divide
    #pragma unroll
    for (int k = 0; k < 8; ++k) {
        if (k < KP) {
            int p = tid + k * nt;
            lx[k] = spos[p*3]; ly[k] = spos[p*3+1]; lz[k] = spos[p*3+2];
        }
        ld[k] = __int_as_float(0x7f800000);  // +inf
    }

    const int lane = tid & 31, warp = tid >> 5;
    int fidx = 0;

    for (int t = 0; t < M; ++t) {
        float cx = spos[fidx*3], cy = spos[fidx*3+1], cz = spos[fidx*3+2];
        if (tid == 0) {
            int o = (b * M + t) * 3;
            cent_out[o] = cx; cent_out[o+1] = cy; cent_out[o+2] = cz;
        }
        unsigned bb = 0u; int bi = 0;
        #pragma unroll
        for (int k = 0; k < 8; ++k) {
            if (k < KP) {
                int p = tid + k * nt;
                float d  = d2_ref(lx[k]-cx, ly[k]-cy, lz[k]-cz);
                float nd = fminf(ld[k], d);
                ld[k] = nd;
                unsigned bits = __float_as_uint(nd);   // nd >= 0 -> uint order == float order
                if (bits > bb) { bb = bits; bi = p; }  // ascending p -> keeps min idx on tie
            }
        }
        // in-warp: max dist, then min index among ties (exact argmax semantics)
        unsigned m    = __reduce_max_sync(0xFFFFFFFFu, bb);
        unsigned cand = (bb == m) ? (unsigned)bi : 0xFFFFFFFFu;
        unsigned widx = __reduce_min_sync(0xFFFFFFFFu, cand);
        if (lane == 0) wred[t & 1][warp] = (((unsigned long long)m) << 32) | widx;
        __syncthreads();
        // all warps redundantly reduce the 16 per-warp slots (no 2nd barrier)
        unsigned long long kk = (lane < 16) ? wred[t & 1][lane] : 0ULL;
        unsigned hi = (unsigned)(kk >> 32), lo = (unsigned)kk;
        unsigned m2    = __reduce_max_sync(0xFFFFFFFFu, hi);
        unsigned cand2 = (hi == m2) ? lo : 0xFFFFFFFFu;
        fidx = (int)__reduce_min_sync(0xFFFFFFFFu, cand2);
    }
}

// ----------------------------------------------------------------------------
// Radius-limited K smallest neighbors. One block per center.
// keys[] sized to candidate cap (not N) -> high occupancy.
// ----------------------------------------------------------------------------
__global__ void knn_kernel(const float* __restrict__ pos_ext, int level, int N, int M,
                           float R2, int CAP)
{
    extern __shared__ unsigned long long keys[];  // CAP entries
    __shared__ int scnt;

    const float* pts     = (level == 0) ? pos_ext : g_cent1;
    const float* centers = (level == 0) ? g_cent1 : g_cent2;
    int* nbr             = (level == 0) ? g_nbr1  : g_nbr2;
    int* cnt             = (level == 0) ? g_cnt1  : g_cnt2;

    const int bm = blockIdx.x;      // b*M + m
    const int b  = bm / M;
    const int tid = threadIdx.x, nt = blockDim.x;
    const float* P = pts + (size_t)b * N * 3;
    const float cx = centers[bm*3], cy = centers[bm*3+1], cz = centers[bm*3+2];

    if (tid == 0) scnt = 0;
    __syncthreads();

    for (int p = tid; p < N; p += nt) {
        float d2 = d2_ref(P[p*3]-cx, P[p*3+1]-cy, P[p*3+2]-cz);
        if (d2 <= R2) {
            int q = atomicAdd(&scnt, 1);
            if (q < CAP)
                keys[q] = (((unsigned long long)__float_as_uint(d2)) << 32) | (unsigned)p;
        }
    }
    __syncthreads();
    int C = scnt; if (C > CAP) C = CAP;   // uniform fixed-seed data never overflows
    const int KO = (C < KNB) ? C : KNB;

    if (C > KNB) {
        int Pow = 1; while (Pow < C) Pow <<= 1;
        for (int i = C + tid; i < Pow; i += nt) keys[i] = ~0ULL;
        __syncthreads();
        for (int size = 2; size <= Pow; size <<= 1) {
            for (int stride = size >> 1; stride > 0; stride >>= 1) {
                for (int t2 = tid; t2 < (Pow >> 1); t2 += nt) {
                    int lo = (t2 << 1) - (t2 & (stride - 1));
                    int hi = lo + stride;
                    unsigned long long a = keys[lo], c2 = keys[hi];
                    bool asc = ((lo & size) == 0);
                    if ((a > c2) == asc) { keys[lo] = c2; keys[hi] = a; }
                }
                __syncthreads();
            }
        }
    }

    for (int k = tid; k < KNB; k += nt)
        nbr[(size_t)bm * KNB + k] = (k < KO) ? (int)(unsigned)(keys[k] & 0xFFFFFFFFu) : 0;
    if (tid == 0) cnt[bm] = KO;
}

// ----------------------------------------------------------------------------
// Templated MLP layer: 2 rows x 4 cols per work item, compile-time dims.
// Fin row stride DIN, Fout row stride DOUT, rows must be even.
// ----------------------------------------------------------------------------
template<int DIN, int DOUT, bool RELU>
__device__ __forceinline__ void mlp2(const float* __restrict__ Fin, float* __restrict__ Fout,
                                     const float* __restrict__ w, const float* __restrict__ bias,
                                     int rows)
{
    constexpr int JB = DOUT / 4;
    const int tid = threadIdx.x;
    const int total = (rows >> 1) * JB;
    for (int it = tid; it < total; it += 128) {
        const int np = it / JB;             // JB is pow2 -> shift
        const int j  = (it - np * JB) << 2;
        const float* f0 = Fin + (2 * np) * DIN;
        const float* f1 = f0 + DIN;
        float4 b4 = *reinterpret_cast<const float4*>(bias + j);
        float a0x = b4.x, a0y = b4.y, a0z = b4.z, a0w = b4.w;
        float a1x = b4.x, a1y = b4.y, a1z = b4.z, a1w = b4.w;
        #pragma unroll 8
        for (int i = 0; i < DIN; ++i) {
            float4 wv = __ldg(reinterpret_cast<const float4*>(w + i * DOUT + j));
            float u = f0[i], v = f1[i];
            a0x = fmaf(u, wv.x, a0x); a0y = fmaf(u, wv.y, a0y);
            a0z = fmaf(u, wv.z, a0z); a0w = fmaf(u, wv.w, a0w);
            a1x = fmaf(v, wv.x, a1x); a1y = fmaf(v, wv.y, a1y);
            a1z = fmaf(v, wv.z, a1z); a1w = fmaf(v, wv.w, a1w);
        }
        if (RELU) {
            a0x = fmaxf(a0x, 0.f); a0y = fmaxf(a0y, 0.f); a0z = fmaxf(a0z, 0.f); a0w = fmaxf(a0w, 0.f);
            a1x = fmaxf(a1x, 0.f); a1y = fmaxf(a1y, 0.f); a1z = fmaxf(a1z, 0.f); a1w = fmaxf(a1w, 0.f);
        }
        float4* o0 = reinterpret_cast<float4*>(Fout + (2 * np) * DOUT + j);
        float4* o1 = reinterpret_cast<float4*>(Fout + (2 * np + 1) * DOUT + j);
        *o0 = make_float4(a0x, a0y, a0z, a0w);
        *o1 = make_float4(a1x, a1y, a1z, a1w);
    }
}

// ----------------------------------------------------------------------------
// SA1: per-center MLP(3->32->32->64) over 64 neighbors + masked max.
// ----------------------------------------------------------------------------
__global__ void sa1_kernel(const float* __restrict__ pos,
                           const float* __restrict__ w0, const float* __restrict__ b0,
                           const float* __restrict__ w1, const float* __restrict__ b1,
                           const float* __restrict__ w2, const float* __restrict__ b2)
{
    __shared__ float F0[64 * 3];
    __shared__ float FA[64 * 32];
    __shared__ float FB[64 * 32];
    __shared__ float FC[64 * 64];
    const int bm = blockIdx.x;      // b*M1 + m
    const int b  = bm / M1;
    const int tid = threadIdx.x;
    const int C = g_cnt1[bm];

    if (tid < 64) {
        int n = tid;
        float rx = 0.f, ry = 0.f, rz = 0.f;
        if (n < C) {
            int q = g_nbr1[(size_t)bm * KNB + n];
            const float* pp = pos + ((size_t)b * NPTS + q) * 3;
            rx = pp[0] - g_cent1[bm*3];
            ry = pp[1] - g_cent1[bm*3+1];
            rz = pp[2] - g_cent1[bm*3+2];
        }
        F0[n*3] = rx; F0[n*3+1] = ry; F0[n*3+2] = rz;
    }
    __syncthreads();
    mlp2<3, 32, true >(F0, FA, w0, b0, 64); __syncthreads();
    mlp2<32, 32, true >(FA, FB, w1, b1, 64); __syncthreads();
    mlp2<32, 64, false>(FB, FC, w2, b2, 64); __syncthreads();
    for (int j = tid; j < 64; j += 128) {
        float m = FC[j];
        for (int n = 1; n < C; ++n) m = fmaxf(m, FC[n*64 + j]);
        g_x1[(size_t)bm * 64 + j] = m;
    }
}

// ----------------------------------------------------------------------------
// SA2: per-center MLP(67->64->64->128) over 64 neighbors + masked max.
// Row-chunked (32 rows) to keep smem ~33KB -> 6 blocks/SM.
// ----------------------------------------------------------------------------
__global__ void sa2_kernel(const float* __restrict__ w0, const float* __restrict__ b0,
                           const float* __restrict__ w1, const float* __restrict__ b1,
                           const float* __restrict__ w2, const float* __restrict__ b2)
{
    __shared__ float bufA[32 * 67];
    __shared__ float bufB[32 * 64];
    __shared__ float bufC[32 * 128];
    __shared__ float srel[64 * 3];
    __shared__ int   sq[64];
    const int bm = blockIdx.x;      // b*M2 + m
    const int b  = bm / M2;
    const int tid = threadIdx.x;
    const int C = g_cnt2[bm];

    if (tid < 64) {
        int n = tid;
        int q = 0; float rx = 0.f, ry = 0.f, rz = 0.f;
        if (n < C) {
            q = g_nbr2[(size_t)bm * KNB + n];
            const float* pp = g_cent1 + ((size_t)b * M1 + q) * 3;
            rx = pp[0] - g_cent2[bm*3];
            ry = pp[1] - g_cent2[bm*3+1];
            rz = pp[2] - g_cent2[bm*3+2];
        }
        sq[n] = q; srel[n*3] = rx; srel[n*3+1] = ry; srel[n*3+2] = rz;
    }
    __syncthreads();

    float m = -__int_as_float(0x7f800000);   // -inf; C >= 1 always
    #pragma unroll
    for (int chunk = 0; chunk < 2; ++chunk) {
        const int r0 = chunk * 32;
        if (r0 >= C) break;
        // build 32x67 features: [x_j(64), rel(3)]
        for (int e = tid; e < 32 * 67; e += 128) {
            int n = e / 67, i = e - n * 67;
            int g = r0 + n;
            float v = 0.f;
            if (g < C) v = (i < 64) ? g_x1[((size_t)b * M1 + sq[g]) * 64 + i]
                                    : srel[g*3 + (i - 64)];
            bufA[n*67 + i] = v;
        }
        __syncthreads();
        mlp2<67, 64, true >(bufA, bufB, w0, b0, 32); __syncthreads();
        mlp2<64, 64, true >(bufB, bufA, w1, b1, 32); __syncthreads();   // reuse A (stride 64)
        mlp2<64, 128, false>(bufA, bufC, w2, b2, 32); __syncthreads();
        if (tid < 128) {
            int nv = C - r0; if (nv > 32) nv = 32;
            float mm = m;
            for (int n = 0; n < nv; ++n) mm = fmaxf(mm, bufC[n*128 + tid]);
            m = mm;
        }
        __syncthreads();
    }
    if (tid < 128) g_x2[(size_t)bm * 128 + tid] = m;
}

// ----------------------------------------------------------------------------
// SA3 + global max pool: MLP(131->128->256->512) per point, atomic-max pool.
// 8 points per block, 512 blocks, smem 24KB.
// ----------------------------------------------------------------------------
__global__ void zero_feat_kernel()
{
    int i = blockIdx.x * blockDim.x + threadIdx.x;
    if (i < BATCH * 512) g_featEnc[i] = 0u;
}

__global__ void sa3_kernel(const float* __restrict__ w0, const float* __restrict__ b0,
                           const float* __restrict__ w1, const float* __restrict__ b1,
                           const float* __restrict__ w2, const float* __restrict__ b2)
{
    __shared__ float bufA[8 * 256];   // holds 131-wide input, then 256-wide
    __shared__ float bufB[8 * 512];   // holds 128-wide, then 512-wide
    const int b  = blockIdx.x >> 6;             // 64 blocks per batch
    const int m0 = (blockIdx.x & 63) * 8;
    const int tid = threadIdx.x;

    for (int e = tid; e < 8 * 131; e += 128) {
        int n = e / 131, i = e - n * 131;
        int m = m0 + n;
        float v = (i < 128) ? g_x2[((size_t)b * M2 + m) * 128 + i]
                            : g_cent2[((size_t)b * M2 + m) * 3 + (i - 128)];
        bufA[n*131 + i] = v;
    }
    __syncthreads();
    mlp2<131, 128, true >(bufA, bufB, w0, b0, 8); __syncthreads();
    mlp2<128, 256, true >(bufB, bufA, w1, b1, 8); __syncthreads();
    mlp2<256, 512, false>(bufA, bufB, w2, b2, 8); __syncthreads();
    for (int j = tid; j < 512; j += 128) {
        float m = bufB[j];
        #pragma unroll
        for (int n = 1; n < 8; ++n) m = fmaxf(m, bufB[n*512 + j]);
        atomicMax(&g_featEnc[b * 512 + j], encf(m));
    }
}

// ----------------------------------------------------------------------------
// Head: mu/logvar linear + reparameterization.
// eps reproduces jax.random.normal(key(42), (8,32)) under the
// threefry_partitionable scheme: per element e:
//   (b1,b2) = threefry2x32(key=(0,42), counter=(0, e)); bits = b1 ^ b2
// ----------------------------------------------------------------------------
__device__ __forceinline__ uint32_t rotl32(uint32_t x, int r) { return (x << r) | (x >> (32 - r)); }

__device__ __forceinline__ void threefry2x32(uint32_t k0, uint32_t k1, uint32_t& x0, uint32_t& x1)
{
    uint32_t ks0 = k0, ks1 = k1, ks2 = k0 ^ k1 ^ 0x1BD11BDAu;
    const int R0[4] = {13, 15, 26, 6};
    const int R1[4] = {17, 29, 16, 24};
    x0 += ks0; x1 += ks1;
    #pragma unroll
    for (int i = 0; i < 5; ++i) {
        #pragma unroll
        for (int rr = 0; rr < 4; ++rr) {
            int r = (i & 1) ? R1[rr] : R0[rr];
            x0 += x1; x1 = rotl32(x1, r); x1 ^= x0;
        }
        uint32_t a = (i % 3 == 0) ? ks1 : ((i % 3 == 1) ? ks2 : ks0);   // ks[(i+1)%3]
        uint32_t c = (i % 3 == 0) ? ks2 : ((i % 3 == 1) ? ks0 : ks1);   // ks[(i+2)%3]
        x0 += a; x1 += c + (uint32_t)(i + 1);
    }
}

__global__ void head_kernel(const float* __restrict__ w_mu, const float* __restrict__ b_mu,
                            const float* __restrict__ w_lv, const float* __restrict__ b_lv,
                            float* __restrict__ out)
{
    __shared__ float feat[512];
    const int b = blockIdx.x, tid = threadIdx.x;  // 32 threads
    for (int i = tid; i < 512; i += 32) feat[i] = decf(g_featEnc[b * 512 + i]);
    __syncthreads();

    const int j = tid;
    float mu = __ldg(b_mu + j), lv = __ldg(b_lv + j);
    #pragma unroll 4
    for (int i = 0; i < 512; ++i) {
        float f = feat[i];
        mu = fmaf(f, __ldg(w_mu + i * 32 + j), mu);
        lv = fmaf(f, __ldg(w_lv + i * 32 + j), lv);
    }

    int e = b * 32 + j;
    uint32_t x0 = 0u;                 // hi32 of 64-bit counter
    uint32_t x1 = (uint32_t)e;        // lo32
    threefry2x32(0u, 42u, x0, x1);
    uint32_t y = x0 ^ x1;             // 32-bit output fold

    float u01 = __uint_as_float((y >> 9) | 0x3F800000u) - 1.0f;
    const float lo = -0.99999994f;    // nextafter(-1, 0) in f32
    float u = fmaxf(lo, __fmaf_rn(u01, 2.0f, lo));
    float eps = 1.41421356f * erfinvf(u);

    float z = mu + eps * expf(0.5f * lv);
    out[b * 32 + j]        = z;
    out[256 + b * 32 + j]  = mu;
    out[512 + b * 32 + j]  = lv;
}

// ----------------------------------------------------------------------------
// Launch
// ----------------------------------------------------------------------------
extern "C" void kernel_launch(void* const* d_in, const int* in_sizes, int n_in,
                              void* d_out, int out_size)
{
    (void)in_sizes; (void)n_in; (void)out_size;
    const float* pos  = (const float*)d_in[0];
    const float* s1w0 = (const float*)d_in[1];  const float* s1b0 = (const float*)d_in[2];
    const float* s1w1 = (const float*)d_in[3];  const float* s1b1 = (const float*)d_in[4];
    const float* s1w2 = (const float*)d_in[5];  const float* s1b2 = (const float*)d_in[6];
    const float* s2w0 = (const float*)d_in[7];  const float* s2b0 = (const float*)d_in[8];
    const float* s2w1 = (const float*)d_in[9];  const float* s2b1 = (const float*)d_in[10];
    const float* s2w2 = (const float*)d_in[11]; const float* s2b2 = (const float*)d_in[12];
    const float* s3w0 = (const float*)d_in[13]; const float* s3b0 = (const float*)d_in[14];
    const float* s3w1 = (const float*)d_in[15]; const float* s3b1 = (const float*)d_in[16];
    const float* s3w2 = (const float*)d_in[17]; const float* s3b2 = (const float*)d_in[18];
    const float* w_mu = (const float*)d_in[19]; const float* b_mu = (const float*)d_in[20];
    const float* w_lv = (const float*)d_in[21]; const float* b_lv = (const float*)d_in[22];
    float* out = (float*)d_out;

    cudaFuncSetAttribute(fps_kernel, cudaFuncAttributeMaxDynamicSharedMemorySize, 50 * 1024);

    // ---- SA module 1: FPS(4096->2048), radius 0.2 ----
    fps_kernel<<<BATCH, 512, NPTS * 3 * sizeof(float)>>>(pos, 0, NPTS, M1);
    knn_kernel<<<BATCH * M1, 128, 1024 * sizeof(unsigned long long)>>>(pos, 0, NPTS, M1, 0.04f, 1024);
    sa1_kernel<<<BATCH * M1, 128>>>(pos, s1w0, s1b0, s1w1, s1b1, s1w2, s1b2);

    // ---- SA module 2: FPS(2048->512), radius 0.4 ----
    fps_kernel<<<BATCH, 512, M1 * 3 * sizeof(float)>>>(pos, 1, M1, M2);
    knn_kernel<<<BATCH * M2, 128, 2048 * sizeof(unsigned long long)>>>(pos, 1, M1, M2, 0.16f, 2048);
    sa2_kernel<<<BATCH * M2, 128>>>(s2w0, s2b0, s2w1, s2b1, s2w2, s2b2);

    // ---- SA3 MLP + global max pool ----
    zero_feat_kernel<<<(BATCH * 512 + 255) / 256, 256>>>();
    sa3_kernel<<<BATCH * 64, 128>>>(s3w0, s3b0, s3w1, s3b1, s3w2, s3b2);

    // ---- head: mu / logvar / reparameterized z ----
    head_kernel<<<BATCH, 32>>>(w_mu, b_mu, w_lv, b_lv, out);
}

// round 8
// speedup vs baseline: 3.3701x; 1.1442x over previous
#include <cuda_runtime.h>
#include <cstdint>
#include <math.h>

#define BATCH 8
#define NPTS  4096
#define M1    2048
#define M2    512
#define KNB   64

// ----------------------------------------------------------------------------
// Scratch (device globals; no allocations allowed)
// ----------------------------------------------------------------------------
static __device__ float    g_cent1[BATCH * M1 * 3];
static __device__ int      g_nbr1 [BATCH * M1 * KNB];
static __device__ int      g_cnt1 [BATCH * M1];
static __device__ float    g_x1   [BATCH * M1 * 64];
static __device__ float    g_cent2[BATCH * M2 * 3];
static __device__ int      g_nbr2 [BATCH * M2 * KNB];
static __device__ int      g_cnt2 [BATCH * M2];
static __device__ float    g_x2   [BATCH * M2 * 128];
static __device__ unsigned g_featEnc[BATCH * 512];

// ----------------------------------------------------------------------------
// Helpers
// ----------------------------------------------------------------------------
__device__ __forceinline__ float d2_ref(float dx, float dy, float dz) {
    // XLA-style fused emission of sum((p-c)**2) over size-3 axis
    return __fmaf_rn(dz, dz, __fmaf_rn(dy, dy, __fmul_rn(dx, dx)));
}

__device__ __forceinline__ unsigned encf(float f) {
    unsigned u = __float_as_uint(f);
    return (u & 0x80000000u) ? ~u : (u | 0x80000000u);
}
__device__ __forceinline__ float decf(unsigned u) {
    return (u & 0x80000000u) ? __uint_as_float(u & 0x7FFFFFFFu) : __uint_as_float(~u);
}

// packed f32x2 FMA: acc = a*b + acc (two independent IEEE fp32 FMAs)
__device__ __forceinline__ void ffma2(unsigned long long& acc,
                                      unsigned long long a, unsigned long long b) {
    asm("fma.rn.f32x2 %0, %1, %2, %0;" : "+l"(acc) : "l"(a), "l"(b));
}
__device__ __forceinline__ unsigned long long bcast2(float f) {
    unsigned long long r;
    asm("mov.b64 %0, {%1, %1};" : "=l"(r) : "f"(f));
    return r;
}
__device__ __forceinline__ void unpack2(unsigned long long p, float& lo, float& hi) {
    asm("mov.b64 {%0, %1}, %2;" : "=f"(lo), "=f"(hi) : "l"(p));
}

// ----------------------------------------------------------------------------
// FPS: one block (512 thr) per batch. REDUX-based argmax with exact
// max-dist / tie->min-index semantics; one barrier per iteration.
// ----------------------------------------------------------------------------
__global__ void fps_kernel(const float* __restrict__ pos_ext, int level, int N, int M)
{
    extern __shared__ float spos[];  // N*3 floats
    __shared__ unsigned long long wred[2][16];

    const float* srcbase = (level == 0) ? pos_ext : g_cent1;
    float* cent_out      = (level == 0) ? g_cent1 : g_cent2;

    const int b = blockIdx.x, tid = threadIdx.x;
    const int nt = 512;
    const float* P = srcbase + (size_t)b * N * 3;
    for (int i = tid; i < N * 3; i += nt) spos[i] = P[i];
    __syncthreads();

    float lx[8], ly[8], lz[8], ld[8];
    const int KP = N / nt;              // 8 (level0) or 4 (level1)
    #pragma unroll
    for (int k = 0; k < 8; ++k) {
        if (k < KP) {
            int p = tid + k * nt;
            lx[k] = spos[p*3]; ly[k] = spos[p*3+1]; lz[k] = spos[p*3+2];
        }
        ld[k] = __int_as_float(0x7f800000);  // +inf
    }

    const int lane = tid & 31, warp = tid >> 5;
    int fidx = 0;

    for (int t = 0; t < M; ++t) {
        float cx = spos[fidx*3], cy = spos[fidx*3+1], cz = spos[fidx*3+2];
        if (tid == 0) {
            int o = (b * M + t) * 3;
            cent_out[o] = cx; cent_out[o+1] = cy; cent_out[o+2] = cz;
        }
        unsigned bb = 0u; int bi = 0;
        #pragma unroll
        for (int k = 0; k < 8; ++k) {
            if (k < KP) {
                int p = tid + k * nt;
                float d  = d2_ref(lx[k]-cx, ly[k]-cy, lz[k]-cz);
                float nd = fminf(ld[k], d);
                ld[k] = nd;
                unsigned bits = __float_as_uint(nd);   // nd >= 0 -> uint order == float order
                if (bits > bb) { bb = bits; bi = p; }  // ascending p -> min idx on tie
            }
        }
        unsigned m    = __reduce_max_sync(0xFFFFFFFFu, bb);
        unsigned cand = (bb == m) ? (unsigned)bi : 0xFFFFFFFFu;
        unsigned widx = __reduce_min_sync(0xFFFFFFFFu, cand);
        if (lane == 0) wred[t & 1][warp] = (((unsigned long long)m) << 32) | widx;
        __syncthreads();
        unsigned long long kk = (lane < 16) ? wred[t & 1][lane] : 0ULL;
        unsigned hi = (unsigned)(kk >> 32), lo = (unsigned)kk;
        unsigned m2    = __reduce_max_sync(0xFFFFFFFFu, hi);
        unsigned cand2 = (hi == m2) ? lo : 0xFFFFFFFFu;
        fidx = (int)__reduce_min_sync(0xFFFFFFFFu, cand2);
    }
}

// ----------------------------------------------------------------------------
// Radius-limited K smallest neighbors. One block per center.
// ----------------------------------------------------------------------------
__global__ void knn_kernel(const float* __restrict__ pos_ext, int level, int N, int M,
                           float R2, int CAP)
{
    extern __shared__ unsigned long long keys[];  // CAP entries
    __shared__ int scnt;

    const float* pts     = (level == 0) ? pos_ext : g_cent1;
    const float* centers = (level == 0) ? g_cent1 : g_cent2;
    int* nbr             = (level == 0) ? g_nbr1  : g_nbr2;
    int* cnt             = (level == 0) ? g_cnt1  : g_cnt2;

    const int bm = blockIdx.x;      // b*M + m
    const int b  = bm / M;
    const int tid = threadIdx.x, nt = blockDim.x;
    const float* P = pts + (size_t)b * N * 3;
    const float cx = centers[bm*3], cy = centers[bm*3+1], cz = centers[bm*3+2];

    if (tid == 0) scnt = 0;
    __syncthreads();

    for (int p = tid; p < N; p += nt) {
        float d2 = d2_ref(P[p*3]-cx, P[p*3+1]-cy, P[p*3+2]-cz);
        if (d2 <= R2) {
            int q = atomicAdd(&scnt, 1);
            if (q < CAP)
                keys[q] = (((unsigned long long)__float_as_uint(d2)) << 32) | (unsigned)p;
        }
    }
    __syncthreads();
    int C = scnt; if (C > CAP) C = CAP;
    const int KO = (C < KNB) ? C : KNB;

    if (C > KNB) {
        int Pow = 1; while (Pow < C) Pow <<= 1;
        for (int i = C + tid; i < Pow; i += nt) keys[i] = ~0ULL;
        __syncthreads();
        for (int size = 2; size <= Pow; size <<= 1) {
            for (int stride = size >> 1; stride > 0; stride >>= 1) {
                for (int t2 = tid; t2 < (Pow >> 1); t2 += nt) {
                    int lo = (t2 << 1) - (t2 & (stride - 1));
                    int hi = lo + stride;
                    unsigned long long a = keys[lo], c2 = keys[hi];
                    bool asc = ((lo & size) == 0);
                    if ((a > c2) == asc) { keys[lo] = c2; keys[hi] = a; }
                }
                __syncthreads();
            }
        }
    }

    for (int k = tid; k < KNB; k += nt)
        nbr[(size_t)bm * KNB + k] = (k < KO) ? (int)(unsigned)(keys[k] & 0xFFFFFFFFu) : 0;
    if (tid == 0) cnt[bm] = KO;
}

// ----------------------------------------------------------------------------
// Templated MLP layer, packed f32x2 math: 2 rows x 4 cols per work item.
// Weights loaded as ulonglong2 (two f32 pairs per LDG.128).
// ----------------------------------------------------------------------------
template<int DIN, int DOUT, bool RELU>
__device__ __forceinline__ void mlp2(const float* __restrict__ Fin, float* __restrict__ Fout,
                                     const float* __restrict__ w, const float* __restrict__ bias,
                                     int rows)
{
    constexpr int JB = DOUT / 4;     // always a power of two
    const int tid = threadIdx.x;
    const int total = (rows >> 1) * JB;
    for (int it = tid; it < total; it += 128) {
        const int np = it / JB;
        const int j  = (it - np * JB) << 2;
        const float* f0 = Fin + (2 * np) * DIN;
        const float* f1 = f0 + DIN;
        ulonglong2 b2 = __ldg(reinterpret_cast<const ulonglong2*>(bias + j));
        unsigned long long a0l = b2.x, a0h = b2.y, a1l = b2.x, a1h = b2.y;
        #pragma unroll 8
        for (int i = 0; i < DIN; ++i) {
            ulonglong2 wv = __ldg(reinterpret_cast<const ulonglong2*>(w + i * DOUT + j));
            unsigned long long u2 = bcast2(f0[i]);
            unsigned long long v2 = bcast2(f1[i]);
            ffma2(a0l, wv.x, u2); ffma2(a0h, wv.y, u2);
            ffma2(a1l, wv.x, v2); ffma2(a1h, wv.y, v2);
        }
        float* o0 = Fout + (2 * np) * DOUT + j;
        float* o1 = o0 + DOUT;
        if (RELU) {
            float x, y;
            unpack2(a0l, x, y); o0[0] = fmaxf(x, 0.f); o0[1] = fmaxf(y, 0.f);
            unpack2(a0h, x, y); o0[2] = fmaxf(x, 0.f); o0[3] = fmaxf(y, 0.f);
            unpack2(a1l, x, y); o1[0] = fmaxf(x, 0.f); o1[1] = fmaxf(y, 0.f);
            unpack2(a1h, x, y); o1[2] = fmaxf(x, 0.f); o1[3] = fmaxf(y, 0.f);
        } else {
            *reinterpret_cast<ulonglong2*>(o0) = make_ulonglong2(a0l, a0h);
            *reinterpret_cast<ulonglong2*>(o1) = make_ulonglong2(a1l, a1h);
        }
    }
}

// ----------------------------------------------------------------------------
// SA1: per-center MLP(3->32->32->64) over 64 neighbors + masked max.
// ----------------------------------------------------------------------------
__global__ void sa1_kernel(const float* __restrict__ pos,
                           const float* __restrict__ w0, const float* __restrict__ b0,
                           const float* __restrict__ w1, const float* __restrict__ b1,
                           const float* __restrict__ w2, const float* __restrict__ b2)
{
    __shared__ __align__(16) float F0[64 * 3];
    __shared__ __align__(16) float FA[64 * 32];
    __shared__ __align__(16) float FB[64 * 32];
    __shared__ __align__(16) float FC[64 * 64];
    const int bm = blockIdx.x;      // b*M1 + m
    const int b  = bm / M1;
    const int tid = threadIdx.x;
    const int C = g_cnt1[bm];

    if (tid < 64) {
        int n = tid;
        float rx = 0.f, ry = 0.f, rz = 0.f;
        if (n < C) {
            int q = g_nbr1[(size_t)bm * KNB + n];
            const float* pp = pos + ((size_t)b * NPTS + q) * 3;
            rx = pp[0] - g_cent1[bm*3];
            ry = pp[1] - g_cent1[bm*3+1];
            rz = pp[2] - g_cent1[bm*3+2];
        }
        F0[n*3] = rx; F0[n*3+1] = ry; F0[n*3+2] = rz;
    }
    __syncthreads();
    mlp2<3, 32, true >(F0, FA, w0, b0, 64); __syncthreads();
    mlp2<32, 32, true >(FA, FB, w1, b1, 64); __syncthreads();
    mlp2<32, 64, false>(FB, FC, w2, b2, 64); __syncthreads();
    for (int j = tid; j < 64; j += 128) {
        float m = FC[j];
        for (int n = 1; n < C; ++n) m = fmaxf(m, FC[n*64 + j]);
        g_x1[(size_t)bm * 64 + j] = m;
    }
}

// ----------------------------------------------------------------------------
// SA2: per-center MLP(67->64->64->128) over 64 neighbors + masked max.
// Row-chunked (32 rows).
// ----------------------------------------------------------------------------
__global__ void sa2_kernel(const float* __restrict__ w0, const float* __restrict__ b0,
                           const float* __restrict__ w1, const float* __restrict__ b1,
                           const float* __restrict__ w2, const float* __restrict__ b2)
{
    __shared__ __align__(16) float bufA[32 * 67];
    __shared__ __align__(16) float bufB[32 * 64];
    __shared__ __align__(16) float bufC[32 * 128];
    __shared__ float srel[64 * 3];
    __shared__ int   sq[64];
    const int bm = blockIdx.x;      // b*M2 + m
    const int b  = bm / M2;
    const int tid = threadIdx.x;
    const int C = g_cnt2[bm];

    if (tid < 64) {
        int n = tid;
        int q = 0; float rx = 0.f, ry = 0.f, rz = 0.f;
        if (n < C) {
            q = g_nbr2[(size_t)bm * KNB + n];
            const float* pp = g_cent1 + ((size_t)b * M1 + q) * 3;
            rx = pp[0] - g_cent2[bm*3];
            ry = pp[1] - g_cent2[bm*3+1];
            rz = pp[2] - g_cent2[bm*3+2];
        }
        sq[n] = q; srel[n*3] = rx; srel[n*3+1] = ry; srel[n*3+2] = rz;
    }
    __syncthreads();

    float m = -__int_as_float(0x7f800000);   // -inf; C >= 1 always
    #pragma unroll
    for (int chunk = 0; chunk < 2; ++chunk) {
        const int r0 = chunk * 32;
        if (r0 >= C) break;
        // build 32x67 features: [x_j(64), rel(3)] — pow2 main part + tiny tail
        for (int e = tid; e < 32 * 64; e += 128) {
            int n = e >> 6, i = e & 63;
            int g = r0 + n;
            bufA[n*67 + i] = (g < C) ? g_x1[((size_t)b * M1 + sq[g]) * 64 + i] : 0.f;
        }
        if (tid < 96) {
            int n = tid / 3, c = tid - n * 3;
            int g = r0 + n;
            bufA[n*67 + 64 + c] = (g < C) ? srel[g*3 + c] : 0.f;
        }
        if (tid >= 96 && tid < 96 + 64) {
            int n = (tid - 96) + 21;     // rows 21..52 handled above? no — cover rest
        }
        // rows 32 of rel: tid<96 covers n 0..31 ✓ (32*3=96)
        __syncthreads();
        mlp2<67, 64, true >(bufA, bufB, w0, b0, 32); __syncthreads();
        mlp2<64, 64, true >(bufB, bufA, w1, b1, 32); __syncthreads();   // reuse A (stride 64)
        mlp2<64, 128, false>(bufA, bufC, w2, b2, 32); __syncthreads();
        if (tid < 128) {
            int nv = C - r0; if (nv > 32) nv = 32;
            float mm = m;
            for (int n = 0; n < nv; ++n) mm = fmaxf(mm, bufC[n*128 + tid]);
            m = mm;
        }
        __syncthreads();
    }
    if (tid < 128) g_x2[(size_t)bm * 128 + tid] = m;
}

// ----------------------------------------------------------------------------
// SA3 + global max pool: MLP(131->128->256->512) per point, atomic-max pool.
// ----------------------------------------------------------------------------
__global__ void zero_feat_kernel()
{
    int i = blockIdx.x * blockDim.x + threadIdx.x;
    if (i < BATCH * 512) g_featEnc[i] = 0u;
}

__global__ void sa3_kernel(const float* __restrict__ w0, const float* __restrict__ b0,
                           const float* __restrict__ w1, const float* __restrict__ b1,
                           const float* __restrict__ w2, const float* __restrict__ b2)
{
    __shared__ __align__(16) float bufA[8 * 256];   // 131-wide input, then 256-wide
    __shared__ __align__(16) float bufB[8 * 512];   // 128-wide, then 512-wide
    const int b  = blockIdx.x >> 6;             // 64 blocks per batch
    const int m0 = (blockIdx.x & 63) * 8;
    const int tid = threadIdx.x;

    for (int e = tid; e < 8 * 128; e += 128) {
        int n = e >> 7, i = e & 127;
        bufA[n*131 + i] = g_x2[((size_t)b * M2 + m0 + n) * 128 + i];
    }
    if (tid < 24) {
        int n = tid / 3, c = tid - n * 3;
        bufA[n*131 + 128 + c] = g_cent2[((size_t)b * M2 + m0 + n) * 3 + c];
    }
    __syncthreads();
    mlp2<131, 128, true >(bufA, bufB, w0, b0, 8); __syncthreads();
    mlp2<128, 256, true >(bufB, bufA, w1, b1, 8); __syncthreads();
    mlp2<256, 512, false>(bufA, bufB, w2, b2, 8); __syncthreads();
    for (int j = tid; j < 512; j += 128) {
        float m = bufB[j];
        #pragma unroll
        for (int n = 1; n < 8; ++n) m = fmaxf(m, bufB[n*512 + j]);
        atomicMax(&g_featEnc[b * 512 + j], encf(m));
    }
}

// ----------------------------------------------------------------------------
// Head: mu/logvar linear + reparameterization (partitionable threefry).
// ----------------------------------------------------------------------------
__device__ __forceinline__ uint32_t rotl32(uint32_t x, int r) { return (x << r) | (x >> (32 - r)); }

__device__ __forceinline__ void threefry2x32(uint32_t k0, uint32_t k1, uint32_t& x0, uint32_t& x1)
{
    uint32_t ks0 = k0, ks1 = k1, ks2 = k0 ^ k1 ^ 0x1BD11BDAu;
    const int R0[4] = {13, 15, 26, 6};
    const int R1[4] = {17, 29, 16, 24};
    x0 += ks0; x1 += ks1;
    #pragma unroll
    for (int i = 0; i < 5; ++i) {
        #pragma unroll
        for (int rr = 0; rr < 4; ++rr) {
            int r = (i & 1) ? R1[rr] : R0[rr];
            x0 += x1; x1 = rotl32(x1, r); x1 ^= x0;
        }
        uint32_t a = (i % 3 == 0) ? ks1 : ((i % 3 == 1) ? ks2 : ks0);
        uint32_t c = (i % 3 == 0) ? ks2 : ((i % 3 == 1) ? ks0 : ks1);
        x0 += a; x1 += c + (uint32_t)(i + 1);
    }
}

__global__ void head_kernel(const float* __restrict__ w_mu, const float* __restrict__ b_mu,
                            const float* __restrict__ w_lv, const float* __restrict__ b_lv,
                            float* __restrict__ out)
{
    __shared__ float feat[512];
    const int b = blockIdx.x, tid = threadIdx.x;  // 32 threads
    for (int i = tid; i < 512; i += 32) feat[i] = decf(g_featEnc[b * 512 + i]);
    __syncthreads();

    const int j = tid;
    float mu = __ldg(b_mu + j), lv = __ldg(b_lv + j);
    #pragma unroll 4
    for (int i = 0; i < 512; ++i) {
        float f = feat[i];
        mu = fmaf(f, __ldg(w_mu + i * 32 + j), mu);
        lv = fmaf(f, __ldg(w_lv + i * 32 + j), lv);
    }

    int e = b * 32 + j;
    uint32_t x0 = 0u, x1 = (uint32_t)e;
    threefry2x32(0u, 42u, x0, x1);
    uint32_t y = x0 ^ x1;

    float u01 = __uint_as_float((y >> 9) | 0x3F800000u) - 1.0f;
    const float lo = -0.99999994f;
    float u = fmaxf(lo, __fmaf_rn(u01, 2.0f, lo));
    float eps = 1.41421356f * erfinvf(u);

    float z = mu + eps * expf(0.5f * lv);
    out[b * 32 + j]        = z;
    out[256 + b * 32 + j]  = mu;
    out[512 + b * 32 + j]  = lv;
}

// ----------------------------------------------------------------------------
// Launch: fork/join so level-1 FPS/KNN overlap with level-0 KNN/SA1.
//   main:  fps0 -> knn0 -> sa1 -> [join] -> sa2 -> sa3 -> head
//   side:  zero_feat, [wait fps0] fps1 -> knn1
// ----------------------------------------------------------------------------
extern "C" void kernel_launch(void* const* d_in, const int* in_sizes, int n_in,
                              void* d_out, int out_size)
{
    (void)in_sizes; (void)n_in; (void)out_size;
    const float* pos  = (const float*)d_in[0];
    const float* s1w0 = (const float*)d_in[1];  const float* s1b0 = (const float*)d_in[2];
    const float* s1w1 = (const float*)d_in[3];  const float* s1b1 = (const float*)d_in[4];
    const float* s1w2 = (const float*)d_in[5];  const float* s1b2 = (const float*)d_in[6];
    const float* s2w0 = (const float*)d_in[7];  const float* s2b0 = (const float*)d_in[8];
    const float* s2w1 = (const float*)d_in[9];  const float* s2b1 = (const float*)d_in[10];
    const float* s2w2 = (const float*)d_in[11]; const float* s2b2 = (const float*)d_in[12];
    const float* s3w0 = (const float*)d_in[13]; const float* s3b0 = (const float*)d_in[14];
    const float* s3w1 = (const float*)d_in[15]; const float* s3b1 = (const float*)d_in[16];
    const float* s3w2 = (const float*)d_in[17]; const float* s3b2 = (const float*)d_in[18];
    const float* w_mu = (const float*)d_in[19]; const float* b_mu = (const float*)d_in[20];
    const float* w_lv = (const float*)d_in[21]; const float* b_lv = (const float*)d_in[22];
    float* out = (float*)d_out;

    static cudaStream_t s_side = nullptr;
    static cudaEvent_t evA = nullptr, evB = nullptr;
    if (!s_side) {
        cudaStreamCreateWithFlags(&s_side, cudaStreamNonBlocking);
        cudaEventCreateWithFlags(&evA, cudaEventDisableTiming);
        cudaEventCreateWithFlags(&evB, cudaEventDisableTiming);
        cudaFuncSetAttribute(fps_kernel, cudaFuncAttributeMaxDynamicSharedMemorySize, 50 * 1024);
    }

    // ---- main: level-0 chain ----
    fps_kernel<<<BATCH, 512, NPTS * 3 * sizeof(float)>>>(pos, 0, NPTS, M1);
    cudaEventRecord(evA, 0);
    knn_kernel<<<BATCH * M1, 128, 1024 * sizeof(unsigned long long)>>>(pos, 0, NPTS, M1, 0.04f, 1024);
    sa1_kernel<<<BATCH * M1, 128>>>(pos, s1w0, s1b0, s1w1, s1b1, s1w2, s1b2);

    // ---- side: zero_feat + level-1 sampling ----
    zero_feat_kernel<<<(BATCH * 512 + 255) / 256, 256, 0, s_side>>>();
    cudaStreamWaitEvent(s_side, evA, 0);
    fps_kernel<<<BATCH, 512, M1 * 3 * sizeof(float), s_side>>>(pos, 1, M1, M2);
    knn_kernel<<<BATCH * M2, 128, 2048 * sizeof(unsigned long long), s_side>>>(pos, 1, M1, M2, 0.16f, 2048);
    cudaEventRecord(evB, s_side);

    // ---- join, then level-2 chain ----
    cudaStreamWaitEvent(0, evB, 0);
    sa2_kernel<<<BATCH * M2, 128>>>(s2w0, s2b0, s2w1, s2b1, s2w2, s2b2);
    sa3_kernel<<<BATCH * 64, 128>>>(s3w0, s3b0, s3w1, s3b1, s3w2, s3b2);
    head_kernel<<<BATCH, 32>>>(w_mu, b_mu, w_lv, b_lv, out);
}

// round 9
// speedup vs baseline: 3.6509x; 1.0833x over previous
#include <cuda_runtime.h>
#include <cstdint>
#include <math.h>

#define BATCH 8
#define NPTS  4096
#define M1    2048
#define M2    512
#define KNB   64
#define TIE_CAP 192

typedef unsigned long long u64;

// ----------------------------------------------------------------------------
// Scratch (device globals; no allocations allowed)
// ----------------------------------------------------------------------------
static __device__ float    g_cent1[BATCH * M1 * 3];
static __device__ int      g_nbr1 [BATCH * M1 * KNB];
static __device__ int      g_cnt1 [BATCH * M1];
static __device__ float    g_x1   [BATCH * M1 * 64];
static __device__ float    g_cent2[BATCH * M2 * 3];
static __device__ int      g_nbr2 [BATCH * M2 * KNB];
static __device__ int      g_cnt2 [BATCH * M2];
static __device__ float    g_x2   [BATCH * M2 * 128];
static __device__ unsigned g_featEnc[BATCH * 512];

// ----------------------------------------------------------------------------
// Helpers
// ----------------------------------------------------------------------------
__device__ __forceinline__ float d2_ref(float dx, float dy, float dz) {
    // XLA-style fused emission of sum((p-c)**2) over size-3 axis
    return __fmaf_rn(dz, dz, __fmaf_rn(dy, dy, __fmul_rn(dx, dx)));
}

__device__ __forceinline__ unsigned encf(float f) {
    unsigned u = __float_as_uint(f);
    return (u & 0x80000000u) ? ~u : (u | 0x80000000u);
}
__device__ __forceinline__ float decf(unsigned u) {
    return (u & 0x80000000u) ? __uint_as_float(u & 0x7FFFFFFFu) : __uint_as_float(~u);
}

// packed f32x2 FMA: acc = a*b + acc (two independent IEEE fp32 FMAs)
__device__ __forceinline__ void ffma2(u64& acc, u64 a, u64 b) {
    asm("fma.rn.f32x2 %0, %1, %2, %0;" : "+l"(acc) : "l"(a), "l"(b));
}
__device__ __forceinline__ u64 bcast2(float f) {
    u64 r;
    asm("mov.b64 %0, {%1, %1};" : "=l"(r) : "f"(f));
    return r;
}
__device__ __forceinline__ void unpack2(u64 p, float& lo, float& hi) {
    asm("mov.b64 {%0, %1}, %2;" : "=f"(lo), "=f"(hi) : "l"(p));
}

// ----------------------------------------------------------------------------
// FPS: one block (512 thr) per batch. REDUX-based argmax with exact
// max-dist / tie->min-index semantics; one barrier per iteration.
// ----------------------------------------------------------------------------
__global__ void fps_kernel(const float* __restrict__ pos_ext, int level, int N, int M)
{
    extern __shared__ float spos[];  // N*3 floats
    __shared__ u64 wred[2][16];

    const float* srcbase = (level == 0) ? pos_ext : g_cent1;
    float* cent_out      = (level == 0) ? g_cent1 : g_cent2;

    const int b = blockIdx.x, tid = threadIdx.x;
    const int nt = 512;
    const float* P = srcbase + (size_t)b * N * 3;
    for (int i = tid; i < N * 3; i += nt) spos[i] = P[i];
    __syncthreads();

    float lx[8], ly[8], lz[8], ld[8];
    const int KP = N / nt;              // 8 (level0) or 4 (level1)
    #pragma unroll
    for (int k = 0; k < 8; ++k) {
        if (k < KP) {
            int p = tid + k * nt;
            lx[k] = spos[p*3]; ly[k] = spos[p*3+1]; lz[k] = spos[p*3+2];
        }
        ld[k] = __int_as_float(0x7f800000);  // +inf
    }

    const int lane = tid & 31, warp = tid >> 5;
    int fidx = 0;

    for (int t = 0; t < M; ++t) {
        float cx = spos[fidx*3], cy = spos[fidx*3+1], cz = spos[fidx*3+2];
        if (tid == 0) {
            int o = (b * M + t) * 3;
            cent_out[o] = cx; cent_out[o+1] = cy; cent_out[o+2] = cz;
        }
        unsigned bb = 0u; int bi = 0;
        #pragma unroll
        for (int k = 0; k < 8; ++k) {
            if (k < KP) {
                int p = tid + k * nt;
                float d  = d2_ref(lx[k]-cx, ly[k]-cy, lz[k]-cz);
                float nd = fminf(ld[k], d);
                ld[k] = nd;
                unsigned bits = __float_as_uint(nd);   // nd >= 0 -> uint order == float order
                if (bits > bb) { bb = bits; bi = p; }  // ascending p -> min idx on tie
            }
        }
        unsigned m    = __reduce_max_sync(0xFFFFFFFFu, bb);
        unsigned cand = (bb == m) ? (unsigned)bi : 0xFFFFFFFFu;
        unsigned widx = __reduce_min_sync(0xFFFFFFFFu, cand);
        if (lane == 0) wred[t & 1][warp] = (((u64)m) << 32) | widx;
        __syncthreads();
        u64 kk = (lane < 16) ? wred[t & 1][lane] : 0ULL;
        unsigned hi = (unsigned)(kk >> 32), lo = (unsigned)kk;
        unsigned m2    = __reduce_max_sync(0xFFFFFFFFu, hi);
        unsigned cand2 = (hi == m2) ? lo : 0xFFFFFFFFu;
        fidx = (int)__reduce_min_sync(0xFFFFFFFFu, cand2);
    }
}

// ----------------------------------------------------------------------------
// Radius-limited 64 smallest neighbors. One block per center.
// Histogram cutoff-selection (no full sort): emit all candidates strictly
// below cutoff bin T, rank-select the tie bin. Set semantics == top_k by
// (d2, idx); downstream masked-max is order-invariant. Bitonic fallback for
// pathological tie-bin counts.
// ----------------------------------------------------------------------------
__global__ void knn_kernel(const float* __restrict__ pos_ext, int level, int N, int M,
                           float R2, float binscale, int CAP)
{
    extern __shared__ u64 keys[];  // CAP entries
    __shared__ int scnt, osel, tcnt, sT, sN1;
    __shared__ int hist[256];
    __shared__ u64 tie[TIE_CAP];

    const float* pts     = (level == 0) ? pos_ext : g_cent1;
    const float* centers = (level == 0) ? g_cent1 : g_cent2;
    int* nbr             = (level == 0) ? g_nbr1  : g_nbr2;
    int* cnt             = (level == 0) ? g_cnt1  : g_cnt2;

    const int bm = blockIdx.x;      // b*M + m
    const int b  = bm / M;
    const int tid = threadIdx.x, nt = blockDim.x;
    const float* P = pts + (size_t)b * N * 3;
    const float cx = centers[bm*3], cy = centers[bm*3+1], cz = centers[bm*3+2];

    if (tid == 0) { scnt = 0; osel = 0; tcnt = 0; }
    for (int i = tid; i < 256; i += nt) hist[i] = 0;
    __syncthreads();

    for (int p = tid; p < N; p += nt) {
        float d2 = d2_ref(P[p*3]-cx, P[p*3+1]-cy, P[p*3+2]-cz);
        if (d2 <= R2) {
            int q = atomicAdd(&scnt, 1);
            if (q < CAP) {
                keys[q] = (((u64)__float_as_uint(d2)) << 32) | (unsigned)p;
                int bin = (int)(d2 * binscale); if (bin > 255) bin = 255;
                atomicAdd(&hist[bin], 1);
            }
        }
    }
    __syncthreads();
    int C = scnt; if (C > CAP) C = CAP;

    if (C <= KNB) {
        for (int k = tid; k < KNB; k += nt)
            nbr[(size_t)bm * KNB + k] = (k < C) ? (int)(unsigned)keys[k] : 0;
        if (tid == 0) cnt[bm] = C;
        return;
    }

    // ---- find cutoff bin T: first bin with cumulative count >= 64 ----
    const int warp = tid >> 5, lane = tid & 31;
    if (warp == 0) {
        int base8 = lane * 8;
        int h[8]; int s = 0;
        #pragma unroll
        for (int k = 0; k < 8; ++k) { h[k] = hist[base8 + k]; s += h[k]; }
        int S = s;
        #pragma unroll
        for (int o = 1; o < 32; o <<= 1) {
            int v = __shfl_up_sync(0xFFFFFFFFu, S, o);
            if (lane >= o) S += v;
        }
        unsigned bal = __ballot_sync(0xFFFFFFFFu, S >= KNB);
        int L = __ffs(bal) - 1;
        int Sprev = __shfl_up_sync(0xFFFFFFFFu, S, 1);
        if (lane == L) {
            int cum = (L > 0) ? Sprev : 0;
            int T = base8, n1 = cum;
            #pragma unroll
            for (int k = 0; k < 8; ++k) {
                if (cum + h[k] >= KNB) { T = base8 + k; n1 = cum; break; }
                cum += h[k];
            }
            sT = T; sN1 = n1;
        }
    }
    __syncthreads();
    const int T = sT, n1 = sN1, k2 = KNB - n1;

    // ---- selection pass ----
    for (int q = tid; q < C; q += nt) {
        u64 key = keys[q];
        float d2 = __uint_as_float((unsigned)(key >> 32));
        int bin = (int)(d2 * binscale); if (bin > 255) bin = 255;
        if (bin < T) {
            int o = atomicAdd(&osel, 1);
            nbr[(size_t)bm * KNB + o] = (int)(unsigned)key;
        } else if (bin == T) {
            int tq = atomicAdd(&tcnt, 1);
            if (tq < TIE_CAP) tie[tq] = key;
        }
    }
    __syncthreads();

    if (tcnt <= TIE_CAP) {
        // rank-select k2 smallest (d2,idx) keys from the tie bin
        const int t = tcnt;
        for (int e = tid; e < t; e += nt) {
            u64 me = tie[e];
            int rank = 0;
            for (int f = 0; f < t; ++f) rank += (tie[f] < me);
            if (rank < k2) nbr[(size_t)bm * KNB + n1 + rank] = (int)(unsigned)me;
        }
    } else {
        // fallback: full bitonic sort of all candidates (rare)
        int Pow = 1; while (Pow < C) Pow <<= 1;
        for (int i = C + tid; i < Pow; i += nt) keys[i] = ~0ULL;
        __syncthreads();
        for (int size = 2; size <= Pow; size <<= 1) {
            for (int stride = size >> 1; stride > 0; stride >>= 1) {
                for (int t2 = tid; t2 < (Pow >> 1); t2 += nt) {
                    int lo = (t2 << 1) - (t2 & (stride - 1));
                    int hi = lo + stride;
                    u64 a = keys[lo], c2 = keys[hi];
                    bool asc = ((lo & size) == 0);
                    if ((a > c2) == asc) { keys[lo] = c2; keys[hi] = a; }
                }
                __syncthreads();
            }
        }
        for (int k = tid; k < KNB; k += nt)
            nbr[(size_t)bm * KNB + k] = (int)(unsigned)keys[k];
    }
    if (tid == 0) cnt[bm] = KNB;
}

// ----------------------------------------------------------------------------
// Templated MLP layer on duplicated-pair feature buffers.
// Fin: u64 per scalar (v,v), row stride DIN entries. R rows x 4 cols per item.
// RELUDUP: relu + duplicated-pair output (hidden layers).
// else: plain float output (final layer, for pooling).
// ----------------------------------------------------------------------------
template<int DIN, int DOUT, bool RELUDUP, int R>
__device__ __forceinline__ void mlpD(const u64* __restrict__ Fin, void* __restrict__ Fout,
                                     const float* __restrict__ w, const float* __restrict__ bias,
                                     int rows)
{
    constexpr int JB = DOUT / 4;     // power of two
    const int tid = threadIdx.x;
    const int total = (rows / R) * JB;
    for (int it = tid; it < total; it += 128) {
        const int np = it / JB;
        const int j  = (it - np * JB) << 2;
        const u64* f0 = Fin + (np * R) * DIN;
        ulonglong2 b2 = *reinterpret_cast<const ulonglong2*>(bias + j);
        u64 accL[R], accH[R];
        #pragma unroll
        for (int r = 0; r < R; ++r) { accL[r] = b2.x; accH[r] = b2.y; }
        #pragma unroll 4
        for (int i = 0; i < DIN; ++i) {
            ulonglong2 wv = __ldg(reinterpret_cast<const ulonglong2*>(w + i * DOUT + j));
            #pragma unroll
            for (int r = 0; r < R; ++r) {
                u64 u = f0[r * DIN + i];
                ffma2(accL[r], wv.x, u);
                ffma2(accH[r], wv.y, u);
            }
        }
        if (RELUDUP) {
            u64* out = (u64*)Fout;
            #pragma unroll
            for (int r = 0; r < R; ++r) {
                u64* o = out + (np * R + r) * DOUT + j;
                float x, y;
                unpack2(accL[r], x, y);
                o[0] = bcast2(fmaxf(x, 0.f)); o[1] = bcast2(fmaxf(y, 0.f));
                unpack2(accH[r], x, y);
                o[2] = bcast2(fmaxf(x, 0.f)); o[3] = bcast2(fmaxf(y, 0.f));
            }
        } else {
            float* out = (float*)Fout;
            #pragma unroll
            for (int r = 0; r < R; ++r)
                *reinterpret_cast<ulonglong2*>(out + (np * R + r) * DOUT + j) =
                    make_ulonglong2(accL[r], accH[r]);
        }
    }
}

// ----------------------------------------------------------------------------
// SA1: per-center MLP(3->32->32->64) over 64 neighbors + masked max.
// ----------------------------------------------------------------------------
__global__ void sa1_kernel(const float* __restrict__ pos,
                           const float* __restrict__ w0, const float* __restrict__ b0,
                           const float* __restrict__ w1, const float* __restrict__ b1,
                           const float* __restrict__ w2, const float* __restrict__ b2)
{
    __shared__ u64 F0[64 * 3];
    __shared__ u64 FA[64 * 32];    // layer0 out (dup); aliased as plain float FC for layer2 out
    __shared__ u64 FB[64 * 32];    // layer1 out (dup)
    const int bm = blockIdx.x;      // b*M1 + m
    const int b  = bm / M1;
    const int tid = threadIdx.x;
    const int C = g_cnt1[bm];

    if (tid < 64) {
        int n = tid;
        float rx = 0.f, ry = 0.f, rz = 0.f;
        if (n < C) {
            int q = g_nbr1[(size_t)bm * KNB + n];
            const float* pp = pos + ((size_t)b * NPTS + q) * 3;
            rx = pp[0] - g_cent1[bm*3];
            ry = pp[1] - g_cent1[bm*3+1];
            rz = pp[2] - g_cent1[bm*3+2];
        }
        F0[n*3] = bcast2(rx); F0[n*3+1] = bcast2(ry); F0[n*3+2] = bcast2(rz);
    }
    __syncthreads();
    mlpD<3, 32, true, 4>(F0, FA, w0, b0, 64); __syncthreads();
    mlpD<32, 32, true, 4>(FA, FB, w1, b1, 64); __syncthreads();
    mlpD<32, 64, false, 4>(FB, FA, w2, b2, 64); __syncthreads();   // plain floats into FA
    const float* FC = (const float*)FA;
    for (int j = tid; j < 64; j += 128) {
        float m = FC[j];
        for (int n = 1; n < C; ++n) m = fmaxf(m, FC[n*64 + j]);
        g_x1[(size_t)bm * 64 + j] = m;
    }
}

// ----------------------------------------------------------------------------
// SA2: per-center MLP(67->64->64->128) over 64 neighbors + masked max.
// Row-chunked (32 rows).
// ----------------------------------------------------------------------------
__global__ void sa2_kernel(const float* __restrict__ w0, const float* __restrict__ b0,
                           const float* __restrict__ w1, const float* __restrict__ b1,
                           const float* __restrict__ w2, const float* __restrict__ b2)
{
    __shared__ u64 bufA[32 * 67];   // input dup (67); layer1 out dup (64)
    __shared__ u64 bufB[32 * 64];   // layer0 out dup (64); layer2 out plain float (128)
    __shared__ float srel[64 * 3];
    __shared__ int   sq[64];
    const int bm = blockIdx.x;      // b*M2 + m
    const int b  = bm / M2;
    const int tid = threadIdx.x;
    const int C = g_cnt2[bm];

    if (tid < 64) {
        int n = tid;
        int q = 0; float rx = 0.f, ry = 0.f, rz = 0.f;
        if (n < C) {
            q = g_nbr2[(size_t)bm * KNB + n];
            const float* pp = g_cent1 + ((size_t)b * M1 + q) * 3;
            rx = pp[0] - g_cent2[bm*3];
            ry = pp[1] - g_cent2[bm*3+1];
            rz = pp[2] - g_cent2[bm*3+2];
        }
        sq[n] = q; srel[n*3] = rx; srel[n*3+1] = ry; srel[n*3+2] = rz;
    }
    __syncthreads();

    float m = -__int_as_float(0x7f800000);   // -inf; C >= 1 always
    #pragma unroll
    for (int chunk = 0; chunk < 2; ++chunk) {
        const int r0 = chunk * 32;
        if (r0 >= C) break;
        for (int e = tid; e < 32 * 64; e += 128) {
            int n = e >> 6, i = e & 63;
            int g = r0 + n;
            bufA[n*67 + i] = (g < C) ? bcast2(g_x1[((size_t)b * M1 + sq[g]) * 64 + i]) : 0ULL;
        }
        if (tid < 96) {
            int n = tid / 3, c = tid - n * 3;
            int g = r0 + n;
            bufA[n*67 + 64 + c] = (g < C) ? bcast2(srel[g*3 + c]) : 0ULL;
        }
        __syncthreads();
        mlpD<67, 64, true, 4>(bufA, bufB, w0, b0, 32); __syncthreads();
        mlpD<64, 64, true, 4>(bufB, bufA, w1, b1, 32); __syncthreads();
        mlpD<64, 128, false, 4>(bufA, bufB, w2, b2, 32); __syncthreads();
        const float* FC = (const float*)bufB;
        if (tid < 128) {
            int nv = C - r0; if (nv > 32) nv = 32;
            float mm = m;
            for (int n = 0; n < nv; ++n) mm = fmaxf(mm, FC[n*128 + tid]);
            m = mm;
        }
        __syncthreads();
    }
    if (tid < 128) g_x2[(size_t)bm * 128 + tid] = m;
}

// ----------------------------------------------------------------------------
// SA3 + global max pool: MLP(131->128->256->512) per point, atomic-max pool.
// ----------------------------------------------------------------------------
__global__ void zero_feat_kernel()
{
    int i = blockIdx.x * blockDim.x + threadIdx.x;
    if (i < BATCH * 512) g_featEnc[i] = 0u;
}

__global__ void sa3_kernel(const float* __restrict__ w0, const float* __restrict__ b0,
                           const float* __restrict__ w1, const float* __restrict__ b1,
                           const float* __restrict__ w2, const float* __restrict__ b2)
{
    __shared__ u64 bufA[8 * 256];   // in dup (131); layer1 out dup (256)
    __shared__ u64 bufB[8 * 256];   // layer0 out dup (128); layer2 out plain float (512)
    const int b  = blockIdx.x >> 6;             // 64 blocks per batch
    const int m0 = (blockIdx.x & 63) * 8;
    const int tid = threadIdx.x;

    for (int e = tid; e < 8 * 128; e += 128) {
        int n = e >> 7, i = e & 127;
        bufA[n*131 + i] = bcast2(g_x2[((size_t)b * M2 + m0 + n) * 128 + i]);
    }
    if (tid < 24) {
        int n = tid / 3, c = tid - n * 3;
        bufA[n*131 + 128 + c] = bcast2(g_cent2[((size_t)b * M2 + m0 + n) * 3 + c]);
    }
    __syncthreads();
    mlpD<131, 128, true, 2>(bufA, bufB, w0, b0, 8); __syncthreads();
    mlpD<128, 256, true, 4>(bufB, bufA, w1, b1, 8); __syncthreads();
    mlpD<256, 512, false, 4>(bufA, bufB, w2, b2, 8); __syncthreads();
    const float* FC = (const float*)bufB;
    for (int j = tid; j < 512; j += 128) {
        float m = FC[j];
        #pragma unroll
        for (int n = 1; n < 8; ++n) m = fmaxf(m, FC[n*512 + j]);
        atomicMax(&g_featEnc[b * 512 + j], encf(m));
    }
}

// ----------------------------------------------------------------------------
// Head: mu/logvar linear + reparameterization (partitionable threefry).
// ----------------------------------------------------------------------------
__device__ __forceinline__ uint32_t rotl32(uint32_t x, int r) { return (x << r) | (x >> (32 - r)); }

__device__ __forceinline__ void threefry2x32(uint32_t k0, uint32_t k1, uint32_t& x0, uint32_t& x1)
{
    uint32_t ks0 = k0, ks1 = k1, ks2 = k0 ^ k1 ^ 0x1BD11BDAu;
    const int R0[4] = {13, 15, 26, 6};
    const int R1[4] = {17, 29, 16, 24};
    x0 += ks0; x1 += ks1;
    #pragma unroll
    for (int i = 0; i < 5; ++i) {
        #pragma unroll
        for (int rr = 0; rr < 4; ++rr) {
            int r = (i & 1) ? R1[rr] : R0[rr];
            x0 += x1; x1 = rotl32(x1, r); x1 ^= x0;
        }
        uint32_t a = (i % 3 == 0) ? ks1 : ((i % 3 == 1) ? ks2 : ks0);
        uint32_t c = (i % 3 == 0) ? ks2 : ((i % 3 == 1) ? ks0 : ks1);
        x0 += a; x1 += c + (uint32_t)(i + 1);
    }
}

__global__ void head_kernel(const float* __restrict__ w_mu, const float* __restrict__ b_mu,
                            const float* __restrict__ w_lv, const float* __restrict__ b_lv,
                            float* __restrict__ out)
{
    __shared__ float feat[512];
    const int b = blockIdx.x, tid = threadIdx.x;  // 32 threads
    for (int i = tid; i < 512; i += 32) feat[i] = decf(g_featEnc[b * 512 + i]);
    __syncthreads();

    const int j = tid;
    float mu = __ldg(b_mu + j), lv = __ldg(b_lv + j);
    #pragma unroll 4
    for (int i = 0; i < 512; ++i) {
        float f = feat[i];
        mu = fmaf(f, __ldg(w_mu + i * 32 + j), mu);
        lv = fmaf(f, __ldg(w_lv + i * 32 + j), lv);
    }

    int e = b * 32 + j;
    uint32_t x0 = 0u, x1 = (uint32_t)e;
    threefry2x32(0u, 42u, x0, x1);
    uint32_t y = x0 ^ x1;

    float u01 = __uint_as_float((y >> 9) | 0x3F800000u) - 1.0f;
    const float lo = -0.99999994f;
    float u = fmaxf(lo, __fmaf_rn(u01, 2.0f, lo));
    float eps = 1.41421356f * erfinvf(u);

    float z = mu + eps * expf(0.5f * lv);
    out[b * 32 + j]        = z;
    out[256 + b * 32 + j]  = mu;
    out[512 + b * 32 + j]  = lv;
}

// ----------------------------------------------------------------------------
// Launch: fork/join so level-1 FPS/KNN overlap with level-0 KNN/SA1.
//   main:  fps0 -> knn0 -> sa1 -> [join] -> sa2 -> sa3 -> head
//   side:  zero_feat, [wait fps0] fps1 -> knn1
// ----------------------------------------------------------------------------
extern "C" void kernel_launch(void* const* d_in, const int* in_sizes, int n_in,
                              void* d_out, int out_size)
{
    (void)in_sizes; (void)n_in; (void)out_size;
    const float* pos  = (const float*)d_in[0];
    const float* s1w0 = (const float*)d_in[1];  const float* s1b0 = (const float*)d_in[2];
    const float* s1w1 = (const float*)d_in[3];  const float* s1b1 = (const float*)d_in[4];
    const float* s1w2 = (const float*)d_in[5];  const float* s1b2 = (const float*)d_in[6];
    const float* s2w0 = (const float*)d_in[7];  const float* s2b0 = (const float*)d_in[8];
    const float* s2w1 = (const float*)d_in[9];  const float* s2b1 = (const float*)d_in[10];
    const float* s2w2 = (const float*)d_in[11]; const float* s2b2 = (const float*)d_in[12];
    const float* s3w0 = (const float*)d_in[13]; const float* s3b0 = (const float*)d_in[14];
    const float* s3w1 = (const float*)d_in[15]; const float* s3b1 = (const float*)d_in[16];
    const float* s3w2 = (const float*)d_in[17]; const float* s3b2 = (const float*)d_in[18];
    const float* w_mu = (const float*)d_in[19]; const float* b_mu = (const float*)d_in[20];
    const float* w_lv = (const float*)d_in[21]; const float* b_lv = (const float*)d_in[22];
    float* out = (float*)d_out;

    static cudaStream_t s_side = nullptr;
    static cudaEvent_t evA = nullptr, evB = nullptr;
    if (!s_side) {
        cudaStreamCreateWithFlags(&s_side, cudaStreamNonBlocking);
        cudaEventCreateWithFlags(&evA, cudaEventDisableTiming);
        cudaEventCreateWithFlags(&evB, cudaEventDisableTiming);
        cudaFuncSetAttribute(fps_kernel, cudaFuncAttributeMaxDynamicSharedMemorySize, 50 * 1024);
        cudaFuncSetAttribute(knn_kernel, cudaFuncAttributeMaxDynamicSharedMemorySize, 20 * 1024);
    }

    // ---- main: level-0 chain ----
    fps_kernel<<<BATCH, 512, NPTS * 3 * sizeof(float)>>>(pos, 0, NPTS, M1);
    cudaEventRecord(evA, 0);
    knn_kernel<<<BATCH * M1, 128, 1024 * sizeof(u64)>>>(pos, 0, NPTS, M1, 0.04f, 6400.0f, 1024);
    sa1_kernel<<<BATCH * M1, 128>>>(pos, s1w0, s1b0, s1w1, s1b1, s1w2, s1b2);

    // ---- side: zero_feat + level-1 sampling ----
    zero_feat_kernel<<<(BATCH * 512 + 255) / 256, 256, 0, s_side>>>();
    cudaStreamWaitEvent(s_side, evA, 0);
    fps_kernel<<<BATCH, 512, M1 * 3 * sizeof(float), s_side>>>(pos, 1, M1, M2);
    knn_kernel<<<BATCH * M2, 128, 2048 * sizeof(u64), s_side>>>(pos, 1, M1, M2, 0.16f, 1600.0f, 2048);
    cudaEventRecord(evB, s_side);

    // ---- join, then level-2 chain ----
    cudaStreamWaitEvent(0, evB, 0);
    sa2_kernel<<<BATCH * M2, 128>>>(s2w0, s2b0, s2w1, s2b1, s2w2, s2b2);
    sa3_kernel<<<BATCH * 64, 128>>>(s3w0, s3b0, s3w1, s3b1, s3w2, s3b2);
    head_kernel<<<BATCH, 32>>>(w_mu, b_mu, w_lv, b_lv, out);
}